// round 3
// baseline (speedup 1.0000x reference)
#include <cuda_runtime.h>

typedef unsigned long long ull;

#define HN 32
#define WARPS 8

__device__ __forceinline__ ull pk2(float x, float y) {
    ull r; asm("mov.b64 %0, {%1,%2};" : "=l"(r) : "f"(x), "f"(y)); return r;
}
__device__ __forceinline__ void upk2(ull v, float& x, float& y) {
    asm("mov.b64 {%0,%1}, %2;" : "=f"(x), "=f"(y) : "l"(v));
}
__device__ __forceinline__ ull ffma2(ull a, ull b, ull c) {
    ull d; asm("fma.rn.f32x2 %0, %1, %2, %3;" : "=l"(d) : "l"(a), "l"(b), "l"(c)); return d;
}
__device__ __forceinline__ ull fadd2(ull a, ull b) {
    ull d; asm("add.rn.f32x2 %0, %1, %2;" : "=l"(d) : "l"(a), "l"(b)); return d;
}
__device__ __forceinline__ float lo2(ull v) {
    return __uint_as_float((unsigned)v);   // low register of the pair, zero-cost
}
__device__ __forceinline__ float sigmoid_f(float a) {
    return __fdividef(1.f, 1.f + __expf(-a));
}
__device__ __forceinline__ float tanh_f(float a) {
    // 1 - 2/(e^{2a}+1); correct limits at +/-inf with approx rcp
    float e = __expf(2.f * a);
    return 1.f - __fdividef(2.f, e + 1.f);
}

__global__ __launch_bounds__(WARPS * 32, 2)
void gru_bidir_kernel(const float* __restrict__ x,
                      const float* __restrict__ Wih_f, const float* __restrict__ Whh_f,
                      const float* __restrict__ bih_f, const float* __restrict__ bhh_f,
                      const float* __restrict__ Wih_b, const float* __restrict__ Whh_b,
                      const float* __restrict__ bih_b, const float* __restrict__ bhh_b,
                      const float* __restrict__ W1, const float* __restrict__ b1,
                      const float* __restrict__ W2, const float* __restrict__ b2,
                      float* __restrict__ out, int B, int T)
{
    __shared__ float sx[WARPS][512];        // per-warp x row (T <= 512)
    __shared__ ull   hd[WARPS][2][HN];      // double-buffered duplicated h pairs
    __shared__ float scat[WARPS][2 * HN];   // [h_fwd | h_bwd] for the head

    const int w    = threadIdx.x >> 5;
    const int lane = threadIdx.x & 31;
    const int b    = blockIdx.x * WARPS + w;
    if (b >= B) return;   // no block-level syncs anywhere: safe early exit

    // ---- stage x[b, :] into shared (coalesced float4) ----
    {
        const float4* xr = reinterpret_cast<const float4*>(x + (size_t)b * T);
        float4* dst = reinterpret_cast<float4*>(sx[w]);
        for (int i = lane; i < (T >> 2); i += 32) dst[i] = xr[i];
    }

    // ---- recurrent weights for rows (lane, lane+32) packed, row lane+64 scalar ----
    ull   wrz[HN];
    float wn[HN];
#pragma unroll
    for (int j = 0; j < HN; j++) {
        wrz[j] = pk2(__ldg(&Whh_f[lane * HN + j]), __ldg(&Whh_f[(lane + 32) * HN + j]));
        wn[j]  = __ldg(&Whh_f[(lane + 64) * HN + j]);
    }
    // combined biases: gate arg = x*wih + (bih + bhh) + h.Whh  (for r,z)
    const ull   bias_rz = pk2(bih_f[lane] + bhh_f[lane],
                              bih_f[lane + 32] + bhh_f[lane + 32]);
    const ull   wih_rz  = pk2(Wih_f[lane], Wih_f[lane + 32]);
    const float wih_n   = Wih_f[lane + 64];
    const float bih_n   = bih_f[lane + 64];
    const float bhh_n   = bhh_f[lane + 64];

    // ---- init h = 0 ----
    float hself = 0.f;
    hd[w][0][lane] = 0ull;
    __syncwarp();

    // ---- forward scan ----
#pragma unroll 2
    for (int t = 0; t < T; t++) {
        const ull* hc = hd[w][t & 1];
        const float xv = sx[w][t];

        // matvec: 2 partial accumulators per stream to break the dep chain
        ull   a0 = bias_rz, a1 = pk2(0.f, 0.f);
        float n0 = bhh_n,   n1 = 0.f;
#pragma unroll
        for (int j = 0; j < HN; j += 2) {
            ull h0 = hc[j];
            ull h1 = hc[j + 1];
            a0 = ffma2(wrz[j],     h0, a0);
            n0 = fmaf (wn[j],  lo2(h0), n0);
            a1 = ffma2(wrz[j + 1], h1, a1);
            n1 = fmaf (wn[j + 1], lo2(h1), n1);
        }
        ull arz = fadd2(a0, a1);
        arz = ffma2(pk2(xv, xv), wih_rz, arz);   // + x * W_ih (r,z)
        float ar, az;
        upk2(arz, ar, az);

        const float r = sigmoid_f(ar);
        const float z = sigmoid_f(az);
        const float ghn = n0 + n1;                       // h.W_hn + b_hhn
        const float an  = fmaf(r, ghn, fmaf(xv, wih_n, bih_n));
        const float n   = tanh_f(an);
        const float hnew = fmaf(z, hself - n, n);        // (1-z)n + z h

        hself = hnew;
        hd[w][(t + 1) & 1][lane] = pk2(hnew, hnew);
        __syncwarp();
    }

    // ---- backward direction: exactly ONE step from h0=0 consuming x[T-1] ----
    {
        const float xl = sx[w][T - 1];
        const float ar = fmaf(xl, Wih_b[lane],      bih_b[lane])      + bhh_b[lane];
        const float az = fmaf(xl, Wih_b[lane + 32], bih_b[lane + 32]) + bhh_b[lane + 32];
        const float an0 = fmaf(xl, Wih_b[lane + 64], bih_b[lane + 64]);
        const float r = sigmoid_f(ar);
        const float z = sigmoid_f(az);
        const float n = tanh_f(fmaf(r, bhh_b[lane + 64], an0));
        const float hb = (1.f - z) * n;

        scat[w][lane]      = hself;   // forward final hidden
        scat[w][HN + lane] = hb;      // backward "last" hidden
    }
    __syncwarp();

    // ---- MLP head: Linear(64,16) -> ReLU -> Linear(16,1) -> Sigmoid ----
    float v = 0.f;
    if (lane < 16) {
        float a = b1[lane];
        const float* w1r = W1 + lane * 64;
#pragma unroll
        for (int k = 0; k < 64; k++) a = fmaf(scat[w][k], __ldg(&w1r[k]), a);
        a = fmaxf(a, 0.f);
        v = a * W2[lane];
    }
#pragma unroll
    for (int off = 16; off; off >>= 1) v += __shfl_xor_sync(0xffffffffu, v, off);
    if (lane == 0) out[b] = sigmoid_f(v + b2[0]);
}

extern "C" void kernel_launch(void* const* d_in, const int* in_sizes, int n_in,
                              void* d_out, int out_size)
{
    const float* x     = (const float*)d_in[0];
    const float* Wih_f = (const float*)d_in[1];
    const float* Whh_f = (const float*)d_in[2];
    const float* bih_f = (const float*)d_in[3];
    const float* bhh_f = (const float*)d_in[4];
    const float* Wih_b = (const float*)d_in[5];
    const float* Whh_b = (const float*)d_in[6];
    const float* bih_b = (const float*)d_in[7];
    const float* bhh_b = (const float*)d_in[8];
    const float* W1    = (const float*)d_in[9];
    const float* b1    = (const float*)d_in[10];
    const float* W2    = (const float*)d_in[11];
    const float* b2    = (const float*)d_in[12];

    const int B = out_size;                 // output is [B, 1] float32
    const int T = in_sizes[0] / B;          // x is [B, T, 1]

    const int blocks = (B + WARPS - 1) / WARPS;
    gru_bidir_kernel<<<blocks, WARPS * 32>>>(x, Wih_f, Whh_f, bih_f, bhh_f,
                                             Wih_b, Whh_b, bih_b, bhh_b,
                                             W1, b1, W2, b2,
                                             (float*)d_out, B, T);
}

// round 4
// speedup vs baseline: 1.0714x; 1.0714x over previous
#include <cuda_runtime.h>

typedef unsigned long long ull;

#define HN 32
#define WARPS 8

__device__ __forceinline__ ull pk2(float x, float y) {
    ull r; asm("mov.b64 %0, {%1,%2};" : "=l"(r) : "f"(x), "f"(y)); return r;
}
__device__ __forceinline__ void upk2(ull v, float& x, float& y) {
    asm("mov.b64 {%0,%1}, %2;" : "=f"(x), "=f"(y) : "l"(v));
}
__device__ __forceinline__ ull ffma2(ull a, ull b, ull c) {
    ull d; asm("fma.rn.f32x2 %0, %1, %2, %3;" : "=l"(d) : "l"(a), "l"(b), "l"(c)); return d;
}
__device__ __forceinline__ ull fadd2(ull a, ull b) {
    ull d; asm("add.rn.f32x2 %0, %1, %2;" : "=l"(d) : "l"(a), "l"(b)); return d;
}
__device__ __forceinline__ ull fmul2(ull a, ull b) {
    ull d; asm("mul.rn.f32x2 %0, %1, %2;" : "=l"(d) : "l"(a), "l"(b)); return d;
}
__device__ __forceinline__ float ex2f(float x) {
    float r; asm("ex2.approx.f32 %0, %1;" : "=f"(r) : "f"(x)); return r;
}
__device__ __forceinline__ float rcpf(float x) {
    float r; asm("rcp.approx.f32 %0, %1;" : "=f"(r) : "f"(x)); return r;
}
__device__ __forceinline__ float sigmoid_f(float a) {
    return rcpf(1.f + ex2f(-1.4426950408889634f * a));
}
__device__ __forceinline__ float tanh_f(float a) {
    // 1 - 2/(e^{2a}+1); correct saturation at +/-inf with approx rcp
    float e = ex2f(2.8853900817779268f * a);
    return fmaf(-2.f, rcpf(e + 1.f), 1.f);
}

__global__ __launch_bounds__(WARPS * 32, 2)
void gru_bidir_kernel(const float* __restrict__ x,
                      const float* __restrict__ Wih_f, const float* __restrict__ Whh_f,
                      const float* __restrict__ bih_f, const float* __restrict__ bhh_f,
                      const float* __restrict__ Wih_b, const float* __restrict__ Whh_b,
                      const float* __restrict__ bih_b, const float* __restrict__ bhh_b,
                      const float* __restrict__ W1, const float* __restrict__ b1,
                      const float* __restrict__ W2, const float* __restrict__ b2,
                      float* __restrict__ out, int B, int T)
{
    __shared__ float sx[WARPS][512];                 // per-warp x row (T <= 512)
    __shared__ alignas(16) float hd[WARPS][2][HN];   // double-buffered plain h
    __shared__ float scat[WARPS][2 * HN];            // [h_fwd | h_bwd] for the head

    const int w    = threadIdx.x >> 5;
    const int lane = threadIdx.x & 31;
    const int b    = blockIdx.x * WARPS + w;
    if (b >= B) return;   // no block-level syncs anywhere: safe early exit

    // ---- stage x[b, :] into shared (coalesced float4) ----
    {
        const float4* xr = reinterpret_cast<const float4*>(x + (size_t)b * T);
        float4* dst = reinterpret_cast<float4*>(sx[w]);
        for (int i = lane; i < (T >> 2); i += 32) dst[i] = xr[i];
    }

    // ---- recurrent weights: pairwise-over-j packing for all 3 gate rows ----
    ull wr[16], wz[16], wn[16];
#pragma unroll
    for (int k = 0; k < 16; k++) {
        wr[k] = pk2(__ldg(&Whh_f[lane * HN + 2 * k]),
                    __ldg(&Whh_f[lane * HN + 2 * k + 1]));
        wz[k] = pk2(__ldg(&Whh_f[(lane + 32) * HN + 2 * k]),
                    __ldg(&Whh_f[(lane + 32) * HN + 2 * k + 1]));
        wn[k] = pk2(__ldg(&Whh_f[(lane + 64) * HN + 2 * k]),
                    __ldg(&Whh_f[(lane + 64) * HN + 2 * k + 1]));
    }
    // accumulator-init pairs: bias folded into lo half
    const ull  ir = pk2(bih_f[lane]      + bhh_f[lane],      0.f);
    const ull  iz = pk2(bih_f[lane + 32] + bhh_f[lane + 32], 0.f);
    const ull  in = pk2(bhh_f[lane + 64],                    0.f);
    const ull  wih_rz = pk2(Wih_f[lane], Wih_f[lane + 32]);
    const float wih_n = Wih_f[lane + 64];
    const float bih_n = bih_f[lane + 64];
    const ull  NL2E = pk2(-1.4426950408889634f, -1.4426950408889634f);
    const ull  ONE2 = pk2(1.f, 1.f);

    // ---- init h = 0 ----
    float hself = 0.f;
    hd[w][0][lane] = 0.f;
    __syncwarp();

    // ---- forward scan ----
#pragma unroll 2
    for (int t = 0; t < T; t++) {
        const ulonglong2* hc = reinterpret_cast<const ulonglong2*>(hd[w][t & 1]);
        const float xv = sx[w][t];

        ull ar = ir, az = iz, an_ = in;
#pragma unroll
        for (int q = 0; q < 8; q++) {
            ulonglong2 hp = hc[q];                 // h[4q..4q+3] as two f32x2
            ar  = ffma2(wr[2 * q],     hp.x, ar);
            az  = ffma2(wz[2 * q],     hp.x, az);
            an_ = ffma2(wn[2 * q],     hp.x, an_);
            ar  = ffma2(wr[2 * q + 1], hp.y, ar);
            az  = ffma2(wz[2 * q + 1], hp.y, az);
            an_ = ffma2(wn[2 * q + 1], hp.y, an_);
        }
        float rlo, rhi, zlo, zhi, nlo, nhi;
        upk2(ar, rlo, rhi); upk2(az, zlo, zhi); upk2(an_, nlo, nhi);

        // cross-pack horizontal sums so (r,z) activation stays packed
        ull arz = fadd2(pk2(rlo, zlo), pk2(rhi, zhi));
        arz = ffma2(pk2(xv, xv), wih_rz, arz);     // + x * W_ih (r,z)

        // packed sigmoid: 1/(1+ex2(-a*log2e))
        ull m = fmul2(arz, NL2E);
        float mr, mz; upk2(m, mr, mz);
        ull dp = fadd2(pk2(ex2f(mr), ex2f(mz)), ONE2);
        float dr, dz; upk2(dp, dr, dz);
        const float r = rcpf(dr);
        const float z = rcpf(dz);

        // n gate
        const float ghn = nlo + nhi;               // h.W_hn + b_hhn
        const float an  = fmaf(r, ghn, fmaf(xv, wih_n, bih_n));
        const float n   = tanh_f(an);
        const float hnew = fmaf(z, hself - n, n);  // (1-z)n + z h

        hself = hnew;
        hd[w][(t + 1) & 1][lane] = hnew;
        __syncwarp();
    }

    // ---- backward direction: exactly ONE step from h0=0 consuming x[T-1] ----
    {
        const float xl = sx[w][T - 1];
        const float ar = fmaf(xl, Wih_b[lane],      bih_b[lane])      + bhh_b[lane];
        const float az = fmaf(xl, Wih_b[lane + 32], bih_b[lane + 32]) + bhh_b[lane + 32];
        const float an0 = fmaf(xl, Wih_b[lane + 64], bih_b[lane + 64]);
        const float r = sigmoid_f(ar);
        const float z = sigmoid_f(az);
        const float n = tanh_f(fmaf(r, bhh_b[lane + 64], an0));
        const float hb = (1.f - z) * n;

        scat[w][lane]      = hself;   // forward final hidden
        scat[w][HN + lane] = hb;      // backward "last" hidden
    }
    __syncwarp();

    // ---- MLP head: Linear(64,16) -> ReLU -> Linear(16,1) -> Sigmoid ----
    float v = 0.f;
    if (lane < 16) {
        float a = b1[lane];
        const float* w1r = W1 + lane * 64;
#pragma unroll
        for (int k = 0; k < 64; k++) a = fmaf(scat[w][k], __ldg(&w1r[k]), a);
        a = fmaxf(a, 0.f);
        v = a * W2[lane];
    }
#pragma unroll
    for (int off = 16; off; off >>= 1) v += __shfl_xor_sync(0xffffffffu, v, off);
    if (lane == 0) out[b] = sigmoid_f(v + b2[0]);
}

extern "C" void kernel_launch(void* const* d_in, const int* in_sizes, int n_in,
                              void* d_out, int out_size)
{
    const float* x     = (const float*)d_in[0];
    const float* Wih_f = (const float*)d_in[1];
    const float* Whh_f = (const float*)d_in[2];
    const float* bih_f = (const float*)d_in[3];
    const float* bhh_f = (const float*)d_in[4];
    const float* Wih_b = (const float*)d_in[5];
    const float* Whh_b = (const float*)d_in[6];
    const float* bih_b = (const float*)d_in[7];
    const float* bhh_b = (const float*)d_in[8];
    const float* W1    = (const float*)d_in[9];
    const float* b1    = (const float*)d_in[10];
    const float* W2    = (const float*)d_in[11];
    const float* b2    = (const float*)d_in[12];

    const int B = out_size;                 // output is [B, 1] float32
    const int T = in_sizes[0] / B;          // x is [B, T, 1]

    const int blocks = (B + WARPS - 1) / WARPS;
    gru_bidir_kernel<<<blocks, WARPS * 32>>>(x, Wih_f, Whh_f, bih_f, bhh_f,
                                             Wih_b, Whh_b, bih_b, bhh_b,
                                             W1, b1, W2, b2,
                                             (float*)d_out, B, T);
}

// round 5
// speedup vs baseline: 1.1254x; 1.0505x over previous
#include <cuda_runtime.h>

typedef unsigned long long ull;

#define HN 32
#define WARPS 4   // warps per block
#define BPW 2     // batch elements per warp

__device__ __forceinline__ ull pk2(float x, float y) {
    ull r; asm("mov.b64 %0, {%1,%2};" : "=l"(r) : "f"(x), "f"(y)); return r;
}
__device__ __forceinline__ void upk2(ull v, float& x, float& y) {
    asm("mov.b64 {%0,%1}, %2;" : "=f"(x), "=f"(y) : "l"(v));
}
__device__ __forceinline__ ull ffma2(ull a, ull b, ull c) {
    ull d; asm("fma.rn.f32x2 %0, %1, %2, %3;" : "=l"(d) : "l"(a), "l"(b), "l"(c)); return d;
}
__device__ __forceinline__ ull fadd2(ull a, ull b) {
    ull d; asm("add.rn.f32x2 %0, %1, %2;" : "=l"(d) : "l"(a), "l"(b)); return d;
}
__device__ __forceinline__ ull fmul2(ull a, ull b) {
    ull d; asm("mul.rn.f32x2 %0, %1, %2;" : "=l"(d) : "l"(a), "l"(b)); return d;
}
__device__ __forceinline__ float ex2f(float x) {
    float r; asm("ex2.approx.f32 %0, %1;" : "=f"(r) : "f"(x)); return r;
}
__device__ __forceinline__ float rcpf(float x) {
    float r; asm("rcp.approx.f32 %0, %1;" : "=f"(r) : "f"(x)); return r;
}
__device__ __forceinline__ float sigmoid_f(float a) {
    return rcpf(1.f + ex2f(-1.4426950408889634f * a));
}
__device__ __forceinline__ float tanh_f(float a) {
    // 1 - 2/(e^{2a}+1); correct saturation at +/-inf with approx rcp
    float e = ex2f(2.8853900817779268f * a);
    return fmaf(-2.f, rcpf(e + 1.f), 1.f);
}

__global__ __launch_bounds__(WARPS * 32, 2)
void gru_bidir_kernel(const float* __restrict__ x,
                      const float* __restrict__ Wih_f, const float* __restrict__ Whh_f,
                      const float* __restrict__ bih_f, const float* __restrict__ bhh_f,
                      const float* __restrict__ Wih_b, const float* __restrict__ Whh_b,
                      const float* __restrict__ bih_b, const float* __restrict__ bhh_b,
                      const float* __restrict__ W1, const float* __restrict__ b1,
                      const float* __restrict__ W2, const float* __restrict__ b2,
                      float* __restrict__ out, int B, int T)
{
    __shared__ float sx[WARPS][BPW][512];                 // per-batch x rows (T <= 512)
    __shared__ alignas(16) float hd[WARPS][BPW][2][HN];   // double-buffered h per batch
    __shared__ float scat[WARPS][2 * HN];                 // head scratch (reused per batch)

    const int w    = threadIdx.x >> 5;
    const int lane = threadIdx.x & 31;
    const int b0   = (blockIdx.x * WARPS + w) * BPW;      // first batch of this warp
    if (b0 >= B) return;   // no block-level syncs anywhere: safe early exit

    // ---- stage x[b0..b0+1, :] into shared (coalesced float4) ----
#pragma unroll
    for (int bi = 0; bi < BPW; bi++) {
        const float4* xr = reinterpret_cast<const float4*>(x + (size_t)(b0 + bi) * T);
        float4* dst = reinterpret_cast<float4*>(sx[w][bi]);
        for (int i = lane; i < (T >> 2); i += 32) dst[i] = xr[i];
    }

    // ---- recurrent weights: pairwise-over-j packing, shared by both batches ----
    ull wr[16], wz[16], wn[16];
#pragma unroll
    for (int k = 0; k < 16; k++) {
        wr[k] = pk2(__ldg(&Whh_f[lane * HN + 2 * k]),
                    __ldg(&Whh_f[lane * HN + 2 * k + 1]));
        wz[k] = pk2(__ldg(&Whh_f[(lane + 32) * HN + 2 * k]),
                    __ldg(&Whh_f[(lane + 32) * HN + 2 * k + 1]));
        wn[k] = pk2(__ldg(&Whh_f[(lane + 64) * HN + 2 * k]),
                    __ldg(&Whh_f[(lane + 64) * HN + 2 * k + 1]));
    }
    const ull  ir = pk2(bih_f[lane]      + bhh_f[lane],      0.f);
    const ull  iz = pk2(bih_f[lane + 32] + bhh_f[lane + 32], 0.f);
    const ull  in = pk2(bhh_f[lane + 64],                    0.f);
    const ull  wih_rz = pk2(Wih_f[lane], Wih_f[lane + 32]);
    const float wih_n = Wih_f[lane + 64];
    const float bih_n = bih_f[lane + 64];
    const ull  NL2E = pk2(-1.4426950408889634f, -1.4426950408889634f);
    const ull  ONE2 = pk2(1.f, 1.f);

    // ---- init h = 0 for both batches ----
    float hself0 = 0.f, hself1 = 0.f;
    hd[w][0][0][lane] = 0.f;
    hd[w][1][0][lane] = 0.f;
    __syncwarp();

    // ---- forward scan: two independent recurrences interleaved ----
#pragma unroll 2
    for (int t = 0; t < T; t++) {
        const ulonglong2* hc0 = reinterpret_cast<const ulonglong2*>(hd[w][0][t & 1]);
        const ulonglong2* hc1 = reinterpret_cast<const ulonglong2*>(hd[w][1][t & 1]);
        const float xv0 = sx[w][0][t];
        const float xv1 = sx[w][1][t];

        ull ar0 = ir, az0 = iz, an0 = in;
        ull ar1 = ir, az1 = iz, an1 = in;
#pragma unroll
        for (int q = 0; q < 8; q++) {
            ulonglong2 hp0 = hc0[q];               // batch0: h[4q..4q+3]
            ulonglong2 hp1 = hc1[q];               // batch1: h[4q..4q+3]
            ar0 = ffma2(wr[2 * q],     hp0.x, ar0);
            ar1 = ffma2(wr[2 * q],     hp1.x, ar1);
            az0 = ffma2(wz[2 * q],     hp0.x, az0);
            az1 = ffma2(wz[2 * q],     hp1.x, az1);
            an0 = ffma2(wn[2 * q],     hp0.x, an0);
            an1 = ffma2(wn[2 * q],     hp1.x, an1);
            ar0 = ffma2(wr[2 * q + 1], hp0.y, ar0);
            ar1 = ffma2(wr[2 * q + 1], hp1.y, ar1);
            az0 = ffma2(wz[2 * q + 1], hp0.y, az0);
            az1 = ffma2(wz[2 * q + 1], hp1.y, az1);
            an0 = ffma2(wn[2 * q + 1], hp0.y, an0);
            an1 = ffma2(wn[2 * q + 1], hp1.y, an1);
        }

        // ---- batch 0 activation ----
        {
            float rlo, rhi, zlo, zhi, nlo, nhi;
            upk2(ar0, rlo, rhi); upk2(az0, zlo, zhi); upk2(an0, nlo, nhi);
            ull arz = fadd2(pk2(rlo, zlo), pk2(rhi, zhi));
            arz = ffma2(pk2(xv0, xv0), wih_rz, arz);
            ull m = fmul2(arz, NL2E);
            float mr, mz; upk2(m, mr, mz);
            ull dp = fadd2(pk2(ex2f(mr), ex2f(mz)), ONE2);
            float dr, dz; upk2(dp, dr, dz);
            const float r = rcpf(dr);
            const float z = rcpf(dz);
            const float ghn = nlo + nhi;
            const float an  = fmaf(r, ghn, fmaf(xv0, wih_n, bih_n));
            const float n   = tanh_f(an);
            hself0 = fmaf(z, hself0 - n, n);
            hd[w][0][(t + 1) & 1][lane] = hself0;
        }
        // ---- batch 1 activation ----
        {
            float rlo, rhi, zlo, zhi, nlo, nhi;
            upk2(ar1, rlo, rhi); upk2(az1, zlo, zhi); upk2(an1, nlo, nhi);
            ull arz = fadd2(pk2(rlo, zlo), pk2(rhi, zhi));
            arz = ffma2(pk2(xv1, xv1), wih_rz, arz);
            ull m = fmul2(arz, NL2E);
            float mr, mz; upk2(m, mr, mz);
            ull dp = fadd2(pk2(ex2f(mr), ex2f(mz)), ONE2);
            float dr, dz; upk2(dp, dr, dz);
            const float r = rcpf(dr);
            const float z = rcpf(dz);
            const float ghn = nlo + nhi;
            const float an  = fmaf(r, ghn, fmaf(xv1, wih_n, bih_n));
            const float n   = tanh_f(an);
            hself1 = fmaf(z, hself1 - n, n);
            hd[w][1][(t + 1) & 1][lane] = hself1;
        }
        __syncwarp();
    }

    // ---- backward direction (ONE step from h0=0 on x[T-1]) + MLP head ----
#pragma unroll
    for (int bi = 0; bi < BPW; bi++) {
        const float xl = sx[w][bi][T - 1];
        const float ar = fmaf(xl, Wih_b[lane],      bih_b[lane])      + bhh_b[lane];
        const float az = fmaf(xl, Wih_b[lane + 32], bih_b[lane + 32]) + bhh_b[lane + 32];
        const float anx = fmaf(xl, Wih_b[lane + 64], bih_b[lane + 64]);
        const float r = sigmoid_f(ar);
        const float z = sigmoid_f(az);
        const float n = tanh_f(fmaf(r, bhh_b[lane + 64], anx));
        const float hb = (1.f - z) * n;

        scat[w][lane]      = (bi == 0) ? hself0 : hself1;  // forward final hidden
        scat[w][HN + lane] = hb;                           // backward "last" hidden
        __syncwarp();

        float v = 0.f;
        if (lane < 16) {
            float a = b1[lane];
            const float* w1r = W1 + lane * 64;
#pragma unroll
            for (int k = 0; k < 64; k++) a = fmaf(scat[w][k], __ldg(&w1r[k]), a);
            a = fmaxf(a, 0.f);
            v = a * W2[lane];
        }
#pragma unroll
        for (int off = 16; off; off >>= 1) v += __shfl_xor_sync(0xffffffffu, v, off);
        if (lane == 0 && b0 + bi < B) out[b0 + bi] = sigmoid_f(v + b2[0]);
        __syncwarp();
    }
}

extern "C" void kernel_launch(void* const* d_in, const int* in_sizes, int n_in,
                              void* d_out, int out_size)
{
    const float* x     = (const float*)d_in[0];
    const float* Wih_f = (const float*)d_in[1];
    const float* Whh_f = (const float*)d_in[2];
    const float* bih_f = (const float*)d_in[3];
    const float* bhh_f = (const float*)d_in[4];
    const float* Wih_b = (const float*)d_in[5];
    const float* Whh_b = (const float*)d_in[6];
    const float* bih_b = (const float*)d_in[7];
    const float* bhh_b = (const float*)d_in[8];
    const float* W1    = (const float*)d_in[9];
    const float* b1    = (const float*)d_in[10];
    const float* W2    = (const float*)d_in[11];
    const float* b2    = (const float*)d_in[12];

    const int B = out_size;                 // output is [B, 1] float32
    const int T = in_sizes[0] / B;          // x is [B, T, 1]

    const int batches_per_block = WARPS * BPW;
    const int blocks = (B + batches_per_block - 1) / batches_per_block;
    gru_bidir_kernel<<<blocks, WARPS * 32>>>(x, Wih_f, Whh_f, bih_f, bhh_f,
                                             Wih_b, Whh_b, bih_b, bhh_b,
                                             W1, b1, W2, b2,
                                             (float*)d_out, B, T);
}

// round 10
// speedup vs baseline: 1.3214x; 1.1742x over previous
#include <cuda_runtime.h>

typedef unsigned long long ull;

#define HN 32
#define WARPS 4   // warps per block
#define BPW 2     // batch elements per warp

__device__ __forceinline__ ull pk2(float x, float y) {
    ull r; asm("mov.b64 %0, {%1,%2};" : "=l"(r) : "f"(x), "f"(y)); return r;
}
__device__ __forceinline__ void upk2(ull v, float& x, float& y) {
    asm("mov.b64 {%0,%1}, %2;" : "=f"(x), "=f"(y) : "l"(v));
}
__device__ __forceinline__ ull ffma2(ull a, ull b, ull c) {
    ull d; asm("fma.rn.f32x2 %0, %1, %2, %3;" : "=l"(d) : "l"(a), "l"(b), "l"(c)); return d;
}
__device__ __forceinline__ float ex2f(float x) {
    float r; asm("ex2.approx.f32 %0, %1;" : "=f"(r) : "f"(x)); return r;
}
__device__ __forceinline__ float rcpf(float x) {
    float r; asm("rcp.approx.f32 %0, %1;" : "=f"(r) : "f"(x)); return r;
}
__device__ __forceinline__ float tanha(float x) {
    float r; asm("tanh.approx.f32 %0, %1;" : "=f"(r) : "f"(x)); return r;
}
// accurate versions (used once, in the backward step + head)
__device__ __forceinline__ float sigmoid_f(float a) {
    return rcpf(1.f + ex2f(-1.4426950408889634f * a));
}
__device__ __forceinline__ float tanh_f(float a) {
    float e = ex2f(2.8853900817779268f * a);
    return fmaf(-2.f, rcpf(e + 1.f), 1.f);
}

__global__ __launch_bounds__(WARPS * 32, 2)
void gru_bidir_kernel(const float* __restrict__ x,
                      const float* __restrict__ Wih_f, const float* __restrict__ Whh_f,
                      const float* __restrict__ bih_f, const float* __restrict__ bhh_f,
                      const float* __restrict__ Wih_b, const float* __restrict__ Whh_b,
                      const float* __restrict__ bih_b, const float* __restrict__ bhh_b,
                      const float* __restrict__ W1, const float* __restrict__ b1,
                      const float* __restrict__ W2, const float* __restrict__ b2,
                      float* __restrict__ out, int B, int T)
{
    __shared__ float sx[WARPS][BPW][512];                 // per-batch x rows (T <= 512)
    __shared__ alignas(16) float hd[WARPS][BPW][2][HN];   // double-buffered h per batch
    __shared__ float scat[WARPS][2 * HN];                 // head scratch (reused per batch)

    const int w    = threadIdx.x >> 5;
    const int lane = threadIdx.x & 31;
    const int b0   = (blockIdx.x * WARPS + w) * BPW;      // first batch of this warp
    if (b0 >= B) return;   // no block-level syncs anywhere: safe early exit

    // ---- stage x[b0..b0+1, :] into shared (coalesced float4) ----
#pragma unroll
    for (int bi = 0; bi < BPW; bi++) {
        const float4* xr = reinterpret_cast<const float4*>(x + (size_t)(b0 + bi) * T);
        float4* dst = reinterpret_cast<float4*>(sx[w][bi]);
        for (int i = lane; i < (T >> 2); i += 32) dst[i] = xr[i];
    }

    // ---- recurrent weights, pairwise-over-j packed; r/z rows prescaled by 0.5
    //      (sigmoid(a) = 0.5*tanh(0.5*a)+0.5, fold the 0.5 into the affine form)
    ull wr[16], wz[16], wn[16];
#pragma unroll
    for (int k = 0; k < 16; k++) {
        wr[k] = pk2(0.5f * __ldg(&Whh_f[lane * HN + 2 * k]),
                    0.5f * __ldg(&Whh_f[lane * HN + 2 * k + 1]));
        wz[k] = pk2(0.5f * __ldg(&Whh_f[(lane + 32) * HN + 2 * k]),
                    0.5f * __ldg(&Whh_f[(lane + 32) * HN + 2 * k + 1]));
        wn[k] = pk2(__ldg(&Whh_f[(lane + 64) * HN + 2 * k]),
                    __ldg(&Whh_f[(lane + 64) * HN + 2 * k + 1]));
    }
    const ull  ir = pk2(0.5f * (bih_f[lane]      + bhh_f[lane]),      0.f);
    const ull  iz = pk2(0.5f * (bih_f[lane + 32] + bhh_f[lane + 32]), 0.f);
    const ull  in = pk2(bhh_f[lane + 64],                             0.f);
    const float wih_r = 0.5f * Wih_f[lane];
    const float wih_z = 0.5f * Wih_f[lane + 32];
    const float wih_n = Wih_f[lane + 64];
    const float bih_n = bih_f[lane + 64];

    // ---- init h = 0 for both batches ----
    float hself0 = 0.f, hself1 = 0.f;
    hd[w][0][0][lane] = 0.f;
    hd[w][1][0][lane] = 0.f;
    __syncwarp();

    // ---- forward scan: two independent recurrences interleaved ----
#pragma unroll 2
    for (int t = 0; t < T; t++) {
        const ulonglong2* hc0 = reinterpret_cast<const ulonglong2*>(hd[w][0][t & 1]);
        const ulonglong2* hc1 = reinterpret_cast<const ulonglong2*>(hd[w][1][t & 1]);
        const float xv0 = sx[w][0][t];
        const float xv1 = sx[w][1][t];

        ull ar0 = ir, az0 = iz, an0 = in;
        ull ar1 = ir, az1 = iz, an1 = in;
#pragma unroll
        for (int q = 0; q < 8; q++) {
            ulonglong2 hp0 = hc0[q];               // batch0: h[4q..4q+3]
            ulonglong2 hp1 = hc1[q];               // batch1: h[4q..4q+3]
            ar0 = ffma2(wr[2 * q],     hp0.x, ar0);
            ar1 = ffma2(wr[2 * q],     hp1.x, ar1);
            az0 = ffma2(wz[2 * q],     hp0.x, az0);
            az1 = ffma2(wz[2 * q],     hp1.x, az1);
            an0 = ffma2(wn[2 * q],     hp0.x, an0);
            an1 = ffma2(wn[2 * q],     hp1.x, an1);
            ar0 = ffma2(wr[2 * q + 1], hp0.y, ar0);
            ar1 = ffma2(wr[2 * q + 1], hp1.y, ar1);
            az0 = ffma2(wz[2 * q + 1], hp0.y, az0);
            az1 = ffma2(wz[2 * q + 1], hp1.y, az1);
            an0 = ffma2(wn[2 * q + 1], hp0.y, an0);
            an1 = ffma2(wn[2 * q + 1], hp1.y, an1);
        }

        // ---- batch 0 activation (MUFU tanh path) ----
        {
            float rlo, rhi, zlo, zhi, nlo, nhi;
            upk2(ar0, rlo, rhi); upk2(az0, zlo, zhi); upk2(an0, nlo, nhi);
            const float r = fmaf(tanha(fmaf(xv0, wih_r, rlo + rhi)), 0.5f, 0.5f);
            const float z = fmaf(tanha(fmaf(xv0, wih_z, zlo + zhi)), 0.5f, 0.5f);
            const float an = fmaf(r, nlo + nhi, fmaf(xv0, wih_n, bih_n));
            const float n  = tanha(an);
            hself0 = fmaf(z, hself0 - n, n);
            hd[w][0][(t + 1) & 1][lane] = hself0;
        }
        // ---- batch 1 activation ----
        {
            float rlo, rhi, zlo, zhi, nlo, nhi;
            upk2(ar1, rlo, rhi); upk2(az1, zlo, zhi); upk2(an1, nlo, nhi);
            const float r = fmaf(tanha(fmaf(xv1, wih_r, rlo + rhi)), 0.5f, 0.5f);
            const float z = fmaf(tanha(fmaf(xv1, wih_z, zlo + zhi)), 0.5f, 0.5f);
            const float an = fmaf(r, nlo + nhi, fmaf(xv1, wih_n, bih_n));
            const float n  = tanha(an);
            hself1 = fmaf(z, hself1 - n, n);
            hd[w][1][(t + 1) & 1][lane] = hself1;
        }
        __syncwarp();
    }

    // ---- backward direction (ONE step from h0=0 on x[T-1]) + MLP head ----
    // accurate activations here: paid once, keeps the head contribution tight
#pragma unroll
    for (int bi = 0; bi < BPW; bi++) {
        const float xl = sx[w][bi][T - 1];
        const float ar = fmaf(xl, Wih_b[lane],      bih_b[lane])      + bhh_b[lane];
        const float az = fmaf(xl, Wih_b[lane + 32], bih_b[lane + 32]) + bhh_b[lane + 32];
        const float anx = fmaf(xl, Wih_b[lane + 64], bih_b[lane + 64]);
        const float r = sigmoid_f(ar);
        const float z = sigmoid_f(az);
        const float n = tanh_f(fmaf(r, bhh_b[lane + 64], anx));
        const float hb = (1.f - z) * n;

        scat[w][lane]      = (bi == 0) ? hself0 : hself1;  // forward final hidden
        scat[w][HN + lane] = hb;                           // backward "last" hidden
        __syncwarp();

        float v = 0.f;
        if (lane < 16) {
            float a = b1[lane];
            const float* w1r = W1 + lane * 64;
#pragma unroll
            for (int k = 0; k < 64; k++) a = fmaf(scat[w][k], __ldg(&w1r[k]), a);
            a = fmaxf(a, 0.f);
            v = a * W2[lane];
        }
#pragma unroll
        for (int off = 16; off; off >>= 1) v += __shfl_xor_sync(0xffffffffu, v, off);
        if (lane == 0 && b0 + bi < B) out[b0 + bi] = sigmoid_f(v + b2[0]);
        __syncwarp();
    }
}

extern "C" void kernel_launch(void* const* d_in, const int* in_sizes, int n_in,
                              void* d_out, int out_size)
{
    const float* x     = (const float*)d_in[0];
    const float* Wih_f = (const float*)d_in[1];
    const float* Whh_f = (const float*)d_in[2];
    const float* bih_f = (const float*)d_in[3];
    const float* bhh_f = (const float*)d_in[4];
    const float* Wih_b = (const float*)d_in[5];
    const float* Whh_b = (const float*)d_in[6];
    const float* bih_b = (const float*)d_in[7];
    const float* bhh_b = (const float*)d_in[8];
    const float* W1    = (const float*)d_in[9];
    const float* b1    = (const float*)d_in[10];
    const float* W2    = (const float*)d_in[11];
    const float* b2    = (const float*)d_in[12];

    const int B = out_size;                 // output is [B, 1] float32
    const int T = in_sizes[0] / B;          // x is [B, T, 1]

    const int batches_per_block = WARPS * BPW;
    const int blocks = (B + batches_per_block - 1) / batches_per_block;
    gru_bidir_kernel<<<blocks, WARPS * 32>>>(x, Wih_f, Whh_f, bih_f, bhh_f,
                                             Wih_b, Whh_b, bih_b, bhh_b,
                                             W1, b1, W2, b2,
                                             (float*)d_out, B, T);
}

// round 12
// speedup vs baseline: 1.3507x; 1.0222x over previous
#include <cuda_runtime.h>

typedef unsigned long long ull;

#define HN 32
#define WARPS 4   // warps per block
#define BPW 4     // batch elements (independent recurrences) per warp

__device__ __forceinline__ ull pk2(float x, float y) {
    ull r; asm("mov.b64 %0, {%1,%2};" : "=l"(r) : "f"(x), "f"(y)); return r;
}
__device__ __forceinline__ void upk2(ull v, float& x, float& y) {
    asm("mov.b64 {%0,%1}, %2;" : "=f"(x), "=f"(y) : "l"(v));
}
__device__ __forceinline__ ull ffma2(ull a, ull b, ull c) {
    ull d; asm("fma.rn.f32x2 %0, %1, %2, %3;" : "=l"(d) : "l"(a), "l"(b), "l"(c)); return d;
}
__device__ __forceinline__ float ex2f(float x) {
    float r; asm("ex2.approx.f32 %0, %1;" : "=f"(r) : "f"(x)); return r;
}
__device__ __forceinline__ float rcpf(float x) {
    float r; asm("rcp.approx.f32 %0, %1;" : "=f"(r) : "f"(x)); return r;
}
__device__ __forceinline__ float tanha(float x) {
    float r; asm("tanh.approx.f32 %0, %1;" : "=f"(r) : "f"(x)); return r;
}
// accurate versions (used once, in the backward step + head)
__device__ __forceinline__ float sigmoid_f(float a) {
    return rcpf(1.f + ex2f(-1.4426950408889634f * a));
}
__device__ __forceinline__ float tanh_f(float a) {
    float e = ex2f(2.8853900817779268f * a);
    return fmaf(-2.f, rcpf(e + 1.f), 1.f);
}

__global__ __launch_bounds__(WARPS * 32, 1)
void gru_bidir_kernel(const float* __restrict__ x,
                      const float* __restrict__ Wih_f, const float* __restrict__ Whh_f,
                      const float* __restrict__ bih_f, const float* __restrict__ bhh_f,
                      const float* __restrict__ Wih_b, const float* __restrict__ Whh_b,
                      const float* __restrict__ bih_b, const float* __restrict__ bhh_b,
                      const float* __restrict__ W1, const float* __restrict__ b1,
                      const float* __restrict__ W2, const float* __restrict__ b2,
                      float* __restrict__ out, int B, int T)
{
    __shared__ float sx[WARPS][BPW][512];                 // per-batch x rows (T <= 512)
    __shared__ alignas(16) float hd[WARPS][BPW][2][HN];   // double-buffered h per batch
    __shared__ float scat[WARPS][2 * HN];                 // head scratch (reused per batch)

    const int w    = threadIdx.x >> 5;
    const int lane = threadIdx.x & 31;
    const int b0   = (blockIdx.x * WARPS + w) * BPW;      // first batch of this warp
    if (b0 >= B) return;   // no block-level syncs anywhere: safe early exit

    // ---- stage x[b0..b0+3, :] into shared (coalesced float4) ----
#pragma unroll
    for (int bi = 0; bi < BPW; bi++) {
        const float4* xr = reinterpret_cast<const float4*>(x + (size_t)(b0 + bi) * T);
        float4* dst = reinterpret_cast<float4*>(sx[w][bi]);
        for (int i = lane; i < (T >> 2); i += 32) dst[i] = xr[i];
    }

    // ---- recurrent weights, pairwise-over-j packed; r/z rows prescaled by 0.5
    //      (sigmoid(a) = 0.5*tanh(0.5*a)+0.5, fold the 0.5 into the affine form)
    ull wr[16], wz[16], wn[16];
#pragma unroll
    for (int k = 0; k < 16; k++) {
        wr[k] = pk2(0.5f * __ldg(&Whh_f[lane * HN + 2 * k]),
                    0.5f * __ldg(&Whh_f[lane * HN + 2 * k + 1]));
        wz[k] = pk2(0.5f * __ldg(&Whh_f[(lane + 32) * HN + 2 * k]),
                    0.5f * __ldg(&Whh_f[(lane + 32) * HN + 2 * k + 1]));
        wn[k] = pk2(__ldg(&Whh_f[(lane + 64) * HN + 2 * k]),
                    __ldg(&Whh_f[(lane + 64) * HN + 2 * k + 1]));
    }
    const ull  ir = pk2(0.5f * (bih_f[lane]      + bhh_f[lane]),      0.f);
    const ull  iz = pk2(0.5f * (bih_f[lane + 32] + bhh_f[lane + 32]), 0.f);
    const ull  in = pk2(bhh_f[lane + 64],                             0.f);
    const float wih_r = 0.5f * Wih_f[lane];
    const float wih_z = 0.5f * Wih_f[lane + 32];
    const float wih_n = Wih_f[lane + 64];
    const float bih_n = bih_f[lane + 64];

    // ---- init h = 0 for all batches ----
    float hself[BPW];
#pragma unroll
    for (int bi = 0; bi < BPW; bi++) {
        hself[bi] = 0.f;
        hd[w][bi][0][lane] = 0.f;
    }
    __syncwarp();

    // ---- forward scan: four independent recurrences interleaved in one warp ----
#pragma unroll 1
    for (int t = 0; t < T; t++) {
        const int cur = t & 1, nxt = cur ^ 1;

        ull ar[BPW], az[BPW], an_[BPW];
        float xv[BPW];
#pragma unroll
        for (int bi = 0; bi < BPW; bi++) {
            ar[bi] = ir; az[bi] = iz; an_[bi] = in;
            xv[bi] = sx[w][bi][t];
        }

#pragma unroll
        for (int q = 0; q < 8; q++) {
            ulonglong2 hp[BPW];
#pragma unroll
            for (int bi = 0; bi < BPW; bi++)
                hp[bi] = reinterpret_cast<const ulonglong2*>(hd[w][bi][cur])[q];
#pragma unroll
            for (int bi = 0; bi < BPW; bi++) {
                ar[bi]  = ffma2(wr[2 * q],     hp[bi].x, ar[bi]);
                az[bi]  = ffma2(wz[2 * q],     hp[bi].x, az[bi]);
                an_[bi] = ffma2(wn[2 * q],     hp[bi].x, an_[bi]);
                ar[bi]  = ffma2(wr[2 * q + 1], hp[bi].y, ar[bi]);
                az[bi]  = ffma2(wz[2 * q + 1], hp[bi].y, az[bi]);
                an_[bi] = ffma2(wn[2 * q + 1], hp[bi].y, an_[bi]);
            }
        }

#pragma unroll
        for (int bi = 0; bi < BPW; bi++) {
            float rlo, rhi, zlo, zhi, nlo, nhi;
            upk2(ar[bi], rlo, rhi); upk2(az[bi], zlo, zhi); upk2(an_[bi], nlo, nhi);
            const float r = fmaf(tanha(fmaf(xv[bi], wih_r, rlo + rhi)), 0.5f, 0.5f);
            const float z = fmaf(tanha(fmaf(xv[bi], wih_z, zlo + zhi)), 0.5f, 0.5f);
            const float an = fmaf(r, nlo + nhi, fmaf(xv[bi], wih_n, bih_n));
            const float n  = tanha(an);
            hself[bi] = fmaf(z, hself[bi] - n, n);
            hd[w][bi][nxt][lane] = hself[bi];
        }
        __syncwarp();
    }

    // ---- backward direction (ONE step from h0=0 on x[T-1]) + MLP head ----
    // accurate activations here: paid once, keeps the head contribution tight
#pragma unroll
    for (int bi = 0; bi < BPW; bi++) {
        const float xl = sx[w][bi][T - 1];
        const float ar = fmaf(xl, Wih_b[lane],      bih_b[lane])      + bhh_b[lane];
        const float az = fmaf(xl, Wih_b[lane + 32], bih_b[lane + 32]) + bhh_b[lane + 32];
        const float anx = fmaf(xl, Wih_b[lane + 64], bih_b[lane + 64]);
        const float r = sigmoid_f(ar);
        const float z = sigmoid_f(az);
        const float n = tanh_f(fmaf(r, bhh_b[lane + 64], anx));
        const float hb = (1.f - z) * n;

        scat[w][lane]      = hself[bi];   // forward final hidden
        scat[w][HN + lane] = hb;          // backward "last" hidden
        __syncwarp();

        float v = 0.f;
        if (lane < 16) {
            float a = b1[lane];
            const float* w1r = W1 + lane * 64;
#pragma unroll
            for (int k = 0; k < 64; k++) a = fmaf(scat[w][k], __ldg(&w1r[k]), a);
            a = fmaxf(a, 0.f);
            v = a * W2[lane];
        }
#pragma unroll
        for (int off = 16; off; off >>= 1) v += __shfl_xor_sync(0xffffffffu, v, off);
        if (lane == 0 && b0 + bi < B) out[b0 + bi] = sigmoid_f(v + b2[0]);
        __syncwarp();
    }
}

extern "C" void kernel_launch(void* const* d_in, const int* in_sizes, int n_in,
                              void* d_out, int out_size)
{
    const float* x     = (const float*)d_in[0];
    const float* Wih_f = (const float*)d_in[1];
    const float* Whh_f = (const float*)d_in[2];
    const float* bih_f = (const float*)d_in[3];
    const float* bhh_f = (const float*)d_in[4];
    const float* Wih_b = (const float*)d_in[5];
    const float* Whh_b = (const float*)d_in[6];
    const float* bih_b = (const float*)d_in[7];
    const float* bhh_b = (const float*)d_in[8];
    const float* W1    = (const float*)d_in[9];
    const float* b1    = (const float*)d_in[10];
    const float* W2    = (const float*)d_in[11];
    const float* b2    = (const float*)d_in[12];

    const int B = out_size;                 // output is [B, 1] float32
    const int T = in_sizes[0] / B;          // x is [B, T, 1]

    const int batches_per_block = WARPS * BPW;
    const int blocks = (B + batches_per_block - 1) / batches_per_block;
    gru_bidir_kernel<<<blocks, WARPS * 32>>>(x, Wih_f, Whh_f, bih_f, bhh_f,
                                             Wih_b, Whh_b, bih_b, bhh_b,
                                             W1, b1, W2, b2,
                                             (float*)d_out, B, T);
}